// round 2
// baseline (speedup 1.0000x reference)
#include <cuda_runtime.h>

// Accumulator for the mean reduction (device global: no allocations allowed).
__device__ double g_acc;

__global__ void k_zero() { g_acc = 0.0; }

__global__ void __launch_bounds__(256)
k_loss(const float* __restrict__ pred, const float* __restrict__ tgt, int n) {
    int i = blockIdx.x * blockDim.x + threadIdx.x;
    float loss = 0.0f;
    if (i < n) {
        const float* p = pred + (size_t)i * 5;
        const float* q = tgt  + (size_t)i * 5;
        float x1 = p[0], y1 = p[1], w1 = p[2], h1 = p[3], a1 = p[4];
        float x2 = q[0], y2 = q[1], w2 = q[2], h2 = q[3], a2 = q[4];

        float c1 = cosf(a1), s1 = sinf(a1);
        float c2 = cosf(a2), s2 = sinf(a2);

        // CCW corner offsets (match reference ordering)
        const float ox[4] = {-0.5f,  0.5f, 0.5f, -0.5f};
        const float oy[4] = {-0.5f, -0.5f, 0.5f,  0.5f};

        // Subject polygon = pred corners; clip polygon = target corners (CCW).
        float inx[8], iny[8], outx[8], outy[8];
        float qx[4], qy[4];
        #pragma unroll
        for (int k = 0; k < 4; k++) {
            float dx = ox[k] * w1, dy = oy[k] * h1;
            inx[k] = x1 + dx * c1 - dy * s1;
            iny[k] = y1 + dx * s1 + dy * c1;
            float ex = ox[k] * w2, ey = oy[k] * h2;
            qx[k] = x2 + ex * c2 - ey * s2;
            qy[k] = y2 + ex * s2 + ey * c2;
        }

        int cnt = 4;
        #pragma unroll
        for (int e = 0; e < 4; e++) {
            float ax = qx[e], ay = qy[e];
            float bx = qx[(e + 1) & 3], by = qy[(e + 1) & 3];
            float ex = bx - ax, ey = by - ay;
            int oc = 0;
            for (int k = 0; k < cnt; k++) {
                int kn = (k + 1 == cnt) ? 0 : k + 1;
                float cx = inx[k],  cy = iny[k];
                float nx = inx[kn], ny = iny[kn];
                float dc = ex * (cy - ay) - ey * (cx - ax);
                float dn = ex * (ny - ay) - ey * (nx - ax);
                bool cin = (dc >= 0.0f), nin = (dn >= 0.0f);
                if (cin) { outx[oc] = cx; outy[oc] = cy; oc++; }
                if (cin != nin) {
                    float t = dc / (dc - dn);
                    outx[oc] = cx + t * (nx - cx);
                    outy[oc] = cy + t * (ny - cy);
                    oc++;
                }
            }
            cnt = oc;
            for (int k = 0; k < cnt; k++) { inx[k] = outx[k]; iny[k] = outy[k]; }
            if (cnt == 0) break;
        }

        float area = 0.0f;
        if (cnt >= 3) {
            float s = 0.0f;
            for (int k = 0; k < cnt; k++) {
                int kn = (k + 1 == cnt) ? 0 : k + 1;
                s += inx[k] * iny[kn] - inx[kn] * iny[k];
            }
            area = 0.5f * fabsf(s);
        }

        float A1 = w1 * h1, A2 = w2 * h2;
        float iou = area / fmaxf(A1 + A2 - area, 1e-10f);
        loss = -logf(fmaxf(iou, 1e-6f));
    }

    // Warp reduce (f32), then block reduce in double, one atomic per block.
    #pragma unroll
    for (int o = 16; o > 0; o >>= 1)
        loss += __shfl_down_sync(0xFFFFFFFFu, loss, o);

    __shared__ double ssum[8];
    int lane = threadIdx.x & 31, warp = threadIdx.x >> 5;
    if (lane == 0) ssum[warp] = (double)loss;
    __syncthreads();
    if (threadIdx.x == 0) {
        double t = 0.0;
        #pragma unroll
        for (int w = 0; w < 8; w++) t += ssum[w];
        atomicAdd(&g_acc, t);
    }
}

__global__ void k_fin(float* out, int n) {
    out[0] = (float)(g_acc / (double)n);
}

extern "C" void kernel_launch(void* const* d_in, const int* in_sizes, int n_in,
                              void* d_out, int out_size) {
    const float* pred = (const float*)d_in[0];
    const float* tgt  = (const float*)d_in[1];
    int n = in_sizes[0] / 5;
    k_zero<<<1, 1>>>();
    k_loss<<<(n + 255) / 256, 256>>>(pred, tgt, n);
    k_fin<<<1, 1>>>((float*)d_out, n);
}

// round 3
// speedup vs baseline: 2.3238x; 2.3238x over previous
#include <cuda_runtime.h>

#define NT 256

__device__ double       g_acc;   // zero-initialized; finalizer resets each run
__device__ unsigned int g_cnt;

__device__ __forceinline__ int clip_sm(const float2 (*in)[NT], float2 (*out)[NT],
                                       int cnt, int tid,
                                       float ex, float ey, float cst) {
    if (cnt == 0) return 0;
    float2 v0 = in[0][tid];
    float  d0 = fmaf(ex, v0.y, fmaf(-ey, v0.x, cst));
    float2 vc = v0; float dc = d0;
    int oc = 0;
    for (int k = 0; k < cnt; k++) {
        float2 vn; float dn;
        if (k + 1 == cnt) { vn = v0; dn = d0; }
        else {
            vn = in[k + 1][tid];
            dn = fmaf(ex, vn.y, fmaf(-ey, vn.x, cst));
        }
        bool cin = (dc >= 0.0f), nin = (dn >= 0.0f);
        if (cin) { out[oc][tid] = vc; oc++; }
        if (cin != nin) {
            float t = dc / (dc - dn);
            out[oc][tid] = make_float2(fmaf(t, vn.x - vc.x, vc.x),
                                       fmaf(t, vn.y - vc.y, vc.y));
            oc++;
        }
        vc = vn; dc = dn;
    }
    return oc;
}

__global__ void __launch_bounds__(NT)
k_loss(const float* __restrict__ pred, const float* __restrict__ tgt,
       float* __restrict__ out, int n, int nblocks) {
    __shared__ float2 bufA[7][NT];   // pass-1 out (<=5), pass-3 out (<=7)
    __shared__ float2 bufB[6][NT];   // pass-2 out (<=6)
    __shared__ double ssum[NT / 32];

    const int tid = threadIdx.x;
    const int i   = blockIdx.x * NT + tid;

    float loss = 0.0f;
    if (i < n) {
        const float* p = pred + (size_t)i * 5;
        const float* q = tgt  + (size_t)i * 5;
        float x1 = __ldg(p+0), y1 = __ldg(p+1), w1 = __ldg(p+2), h1 = __ldg(p+3), a1 = __ldg(p+4);
        float x2 = __ldg(q+0), y2 = __ldg(q+1), w2 = __ldg(q+2), h2 = __ldg(q+3), a2 = __ldg(q+4);

        float s1, c1, s2, c2;
        __sincosf(a1, &s1, &c1);
        __sincosf(a2, &s2, &c2);

        const float ox[4] = {-0.5f,  0.5f, 0.5f, -0.5f};
        const float oy[4] = {-0.5f, -0.5f, 0.5f,  0.5f};

        float px[4], py[4], qx[4], qy[4];
        #pragma unroll
        for (int k = 0; k < 4; k++) {
            float dx = ox[k] * w1, dy = oy[k] * h1;
            px[k] = x1 + dx * c1 - dy * s1;
            py[k] = y1 + dx * s1 + dy * c1;
            float fx = ox[k] * w2, fy = oy[k] * h2;
            qx[k] = x2 + fx * c2 - fy * s2;
            qy[k] = y2 + fx * s2 + fy * c2;
        }

        // ---- pass 1: clip pred quad (registers) by target edge 0 -> bufA ----
        int cnt;
        {
            float ax = qx[0], ay = qy[0];
            float ex = qx[1] - ax, ey = qy[1] - ay;
            float cst = ey * ax - ex * ay;
            float d[4];
            #pragma unroll
            for (int k = 0; k < 4; k++)
                d[k] = fmaf(ex, py[k], fmaf(-ey, px[k], cst));
            int oc = 0;
            #pragma unroll
            for (int k = 0; k < 4; k++) {
                int kn = (k + 1) & 3;
                bool cin = (d[k] >= 0.0f), nin = (d[kn] >= 0.0f);
                if (cin) { bufA[oc][tid] = make_float2(px[k], py[k]); oc++; }
                if (cin != nin) {
                    float t = d[k] / (d[k] - d[kn]);
                    bufA[oc][tid] = make_float2(fmaf(t, px[kn] - px[k], px[k]),
                                                fmaf(t, py[kn] - py[k], py[k]));
                    oc++;
                }
            }
            cnt = oc;
        }

        // ---- pass 2: edge 1, bufA -> bufB ----
        {
            float ax = qx[1], ay = qy[1];
            float ex = qx[2] - ax, ey = qy[2] - ay;
            cnt = clip_sm(bufA, bufB, cnt, tid, ex, ey, ey * ax - ex * ay);
        }
        // ---- pass 3: edge 2, bufB -> bufA ----
        {
            float ax = qx[2], ay = qy[2];
            float ex = qx[3] - ax, ey = qy[3] - ay;
            cnt = clip_sm(bufB, bufA, cnt, tid, ex, ey, ey * ax - ex * ay);
        }

        // ---- pass 4: edge 3, stream shoelace area from emitted vertices ----
        float area = 0.0f;
        if (cnt > 0) {
            float ax = qx[3], ay = qy[3];
            float ex = qx[0] - ax, ey = qy[0] - ay;
            float cst = ey * ax - ex * ay;

            float2 v0 = bufA[0][tid];
            float  d0 = fmaf(ex, v0.y, fmaf(-ey, v0.x, cst));
            float2 vc = v0; float dc = d0;

            float area2 = 0.0f;
            float2 first = make_float2(0.f, 0.f), prev = make_float2(0.f, 0.f);
            int m = 0;
            for (int k = 0; k < cnt; k++) {
                float2 vn; float dn;
                if (k + 1 == cnt) { vn = v0; dn = d0; }
                else {
                    vn = bufA[k + 1][tid];
                    dn = fmaf(ex, vn.y, fmaf(-ey, vn.x, cst));
                }
                bool cin = (dc >= 0.0f), nin = (dn >= 0.0f);
                if (cin) {
                    if (m == 0) first = vc;
                    else area2 += prev.x * vc.y - prev.y * vc.x;
                    prev = vc; m++;
                }
                if (cin != nin) {
                    float t = dc / (dc - dn);
                    float2 ip = make_float2(fmaf(t, vn.x - vc.x, vc.x),
                                            fmaf(t, vn.y - vc.y, vc.y));
                    if (m == 0) first = ip;
                    else area2 += prev.x * ip.y - prev.y * ip.x;
                    prev = ip; m++;
                }
                vc = vn; dc = dn;
            }
            if (m >= 3) {
                area2 += prev.x * first.y - prev.y * first.x;
                area = 0.5f * fabsf(area2);
            }
        }

        float A1 = w1 * h1, A2 = w2 * h2;
        float iou = area / fmaxf(A1 + A2 - area, 1e-10f);
        loss = -__logf(fmaxf(iou, 1e-6f));
    }

    // ---- block reduction ----
    #pragma unroll
    for (int o = 16; o > 0; o >>= 1)
        loss += __shfl_down_sync(0xFFFFFFFFu, loss, o);
    int lane = tid & 31, warp = tid >> 5;
    if (lane == 0) ssum[warp] = (double)loss;
    __syncthreads();

    if (tid == 0) {
        double t = 0.0;
        #pragma unroll
        for (int w = 0; w < NT / 32; w++) t += ssum[w];
        atomicAdd(&g_acc, t);
        __threadfence();
        unsigned int done = atomicAdd(&g_cnt, 1u);
        if (done == (unsigned int)(nblocks - 1)) {
            double acc = atomicAdd(&g_acc, 0.0);   // coherent read via L2
            out[0] = (float)(acc / (double)n);
            atomicExch((unsigned long long*)&g_acc, 0ull);  // reset for next replay
            atomicExch(&g_cnt, 0u);
        }
    }
}

extern "C" void kernel_launch(void* const* d_in, const int* in_sizes, int n_in,
                              void* d_out, int out_size) {
    const float* pred = (const float*)d_in[0];
    const float* tgt  = (const float*)d_in[1];
    int n = in_sizes[0] / 5;
    int nblocks = (n + NT - 1) / NT;
    k_loss<<<nblocks, NT>>>(pred, tgt, (float*)d_out, n, nblocks);
}

// round 5
// speedup vs baseline: 3.0000x; 1.2910x over previous
#include <cuda_runtime.h>

#define NT 256

__device__ double       g_acc;
__device__ unsigned int g_cnt;

__device__ __forceinline__ float frcp(float x) {
    float r; asm("rcp.approx.f32 %0, %1;" : "=f"(r) : "f"(x)); return r;
}

__global__ void __launch_bounds__(NT)
k_loss(const float* __restrict__ pred, const float* __restrict__ tgt,
       float* __restrict__ out, int n, int nblocks) {
    __shared__ double ssum[NT / 32];

    const int tid = threadIdx.x;
    const int i   = blockIdx.x * NT + tid;

    float loss = 0.0f;
    if (i < n) {
        const float* p = pred + (size_t)i * 5;
        const float* q = tgt  + (size_t)i * 5;
        float x1 = p[0], y1 = p[1], hw1 = 0.5f * p[2], hh1 = 0.5f * p[3], a1 = p[4];
        float x2 = q[0], y2 = q[1], hw2 = 0.5f * q[2], hh2 = 0.5f * q[3], a2 = q[4];

        // Work in box2's local frame: clip region is the axis box [±hw2]x[±hh2].
        float sf, cf, s2, c2;
        __sincosf(a1 - a2, &sf, &cf);
        __sincosf(a2, &s2, &c2);
        float ddx = x1 - x2, ddy = y1 - y2;
        float dx = fmaf(ddx, c2, ddy * s2);          // box1 center in box2 frame
        float dy = fmaf(-ddx, s2, ddy * c2);

        // box1 corners in box2 frame (orientation irrelevant: fabs at the end)
        float ux = hw1 * cf, uy = hw1 * sf;
        float vx = -hh1 * sf, vy = hh1 * cf;
        float Px[4], Py[4];
        Px[0] = dx - ux - vx; Py[0] = dy - uy - vy;
        Px[1] = dx + ux - vx; Py[1] = dy + uy - vy;
        Px[2] = dx + ux + vx; Py[2] = dy + uy + vy;
        Px[3] = dx - ux + vx; Py[3] = dy - uy + vy;

        // ---------- pass 1: clip by x-slab [-hw2, hw2] -> 8 slots ----------
        const float lo = -hw2, hi = hw2;
        float Sx[8], Sy[8];
        float lastx = Px[0], lasty = Py[0];
        // iterate pair-start indices {2,3,0,1,2,3}: first two warm `last`,
        // final four write slots 0..7.
        const int idx[6] = {2, 3, 0, 1, 2, 3};
        #pragma unroll
        for (int it = 0; it < 6; it++) {
            int a = idx[it], b = (a + 1) & 3;
            float cx = Px[a], cy = Py[a], nx = Px[b], ny = Py[b];
            bool cLow = cx < lo, cHigh = cx > hi; bool cIn = !cLow && !cHigh;
            bool nLow = nx < lo, nHigh = nx > hi; bool nIn = !nLow && !nHigh;
            bool pad = (cLow & nLow) | (cHigh & nHigh);
            float inv = frcp(nx - cx);
            float dyv = ny - cy;
            float tl = (lo - cx) * inv, th = (hi - cx) * inv;
            float yl = fmaf(tl, dyv, cy), yh = fmaf(th, dyv, cy);
            float nrx = cLow ? lo : hi, nry = cLow ? yl : yh;
            float s0x = cIn ? cx : nrx,  s0y = cIn ? cy : nry;
            s0x = pad ? lastx : s0x;     s0y = pad ? lasty : s0y;
            float frx = nLow ? lo : hi,  fry = nLow ? yl : yh;
            float s1x = nIn ? s0x : frx, s1y = nIn ? s0y : fry;
            s1x = pad ? lastx : s1x;     s1y = pad ? lasty : s1y;
            lastx = s1x; lasty = s1y;
            if (it >= 2) {
                int k = it - 2;
                Sx[2 * k] = s0x; Sy[2 * k] = s0y;
                Sx[2 * k + 1] = s1x; Sy[2 * k + 1] = s1y;
            }
        }

        // ---------- pass 2: clip by y-slab [-hh2, hh2], stream shoelace ----------
        const float lo2 = -hh2, hi2 = hh2;
        float acc = 0.0f;
        float prevx = 0.0f, prevy = 0.0f, Fx = 0.0f, Fy = 0.0f;
        bool started = false;
        #pragma unroll
        for (int k = 0; k < 8; k++) {
            float cx = Sx[k], cy = Sy[k];
            float nx = Sx[(k + 1) & 7], ny = Sy[(k + 1) & 7];
            bool cLow = cy < lo2, cHigh = cy > hi2; bool cIn = !cLow && !cHigh;
            bool nLow = ny < lo2, nHigh = ny > hi2; bool nIn = !nLow && !nHigh;
            bool f = !((cLow & nLow) | (cHigh & nHigh));
            float inv = frcp(ny - cy);
            float dxv = nx - cx;
            float tl = (lo2 - cy) * inv, th = (hi2 - cy) * inv;
            float xl = fmaf(tl, dxv, cx), xh = fmaf(th, dxv, cx);
            float nrx = cLow ? xl : xh, nry = cLow ? lo2 : hi2;
            float e0x = cIn ? cx : nrx, e0y = cIn ? cy : nry;
            float frx = nLow ? xl : xh, fry = nLow ? lo2 : hi2;
            float e1x = nIn ? e0x : frx, e1y = nIn ? e0y : fry;

            // chain: emissions e0, e1 gated by f
            float c0 = fmaf(prevx, e0y, -(prevy * e0x));
            if (f & started) acc += c0;
            if (f & !started) { Fx = e0x; Fy = e0y; }
            if (f) { prevx = e0x; prevy = e0y; }
            started = started | f;
            float c1 = fmaf(prevx, e1y, -(prevy * e1x));
            if (f) { acc += c1; prevx = e1x; prevy = e1y; }
        }
        if (started) acc += fmaf(prevx, Fy, -(prevy * Fx));

        float area = 0.5f * fabsf(acc);
        float A1 = 4.0f * hw1 * hh1, A2 = 4.0f * hw2 * hh2;
        float iou = area / fmaxf(A1 + A2 - area, 1e-10f);
        loss = -__logf(fmaxf(iou, 1e-6f));
    }

    // ---- block reduction (proven in round 3) ----
    #pragma unroll
    for (int o = 16; o > 0; o >>= 1)
        loss += __shfl_down_sync(0xFFFFFFFFu, loss, o);
    int lane = tid & 31, warp = tid >> 5;
    if (lane == 0) ssum[warp] = (double)loss;
    __syncthreads();

    if (tid == 0) {
        double t = 0.0;
        #pragma unroll
        for (int w = 0; w < NT / 32; w++) t += ssum[w];
        atomicAdd(&g_acc, t);
        __threadfence();
        unsigned int done = atomicAdd(&g_cnt, 1u);
        if (done == (unsigned int)(nblocks - 1)) {
            double a = atomicAdd(&g_acc, 0.0);
            out[0] = (float)(a / (double)n);
            atomicExch((unsigned long long*)&g_acc, 0ull);
            atomicExch(&g_cnt, 0u);
        }
    }
}

extern "C" void kernel_launch(void* const* d_in, const int* in_sizes, int n_in,
                              void* d_out, int out_size) {
    const float* pred = (const float*)d_in[0];
    const float* tgt  = (const float*)d_in[1];
    int n = in_sizes[0] / 5;
    int nblocks = (n + NT - 1) / NT;
    k_loss<<<nblocks, NT>>>(pred, tgt, (float*)d_out, n, nblocks);
}

// round 6
// speedup vs baseline: 3.8089x; 1.2696x over previous
#include <cuda_runtime.h>

#define NT 256

__device__ double       g_acc;
__device__ unsigned int g_cnt;

__device__ __forceinline__ float frcp(float x) {
    float r; asm("rcp.approx.f32 %0, %1;" : "=f"(r) : "f"(x)); return r;
}
__device__ __forceinline__ float clampf(float x, float lo, float hi) {
    return fminf(fmaxf(x, lo), hi);
}

__global__ void __launch_bounds__(NT)
k_loss(const float* __restrict__ pred, const float* __restrict__ tgt,
       float* __restrict__ out, int n, int nblocks) {
    __shared__ double ssum[NT / 32];

    const int tid = threadIdx.x;
    const int i   = blockIdx.x * NT + tid;

    float loss = 0.0f;
    if (i < n) {
        const float* p = pred + (size_t)i * 5;
        const float* q = tgt  + (size_t)i * 5;
        float x1 = p[0], y1 = p[1], hw1 = 0.5f * p[2], hh1 = 0.5f * p[3], a1 = p[4];
        float x2 = q[0], y2 = q[1], hw2 = 0.5f * q[2], hh2 = 0.5f * q[3], a2 = q[4];

        // Work in box2's local frame: clip region is the axis box [±hw2]x[±hh2].
        float sf, cf, s2, c2;
        __sincosf(a1 - a2, &sf, &cf);
        __sincosf(a2, &s2, &c2);
        float ddx = x1 - x2, ddy = y1 - y2;
        float dx = fmaf(ddx, c2, ddy * s2);          // box1 center in box2 frame
        float dy = fmaf(-ddx, s2, ddy * c2);

        float ux = hw1 * cf, uy = hw1 * sf;
        float vx = -hh1 * sf, vy = hh1 * cf;
        float Px[4], Py[4];
        Px[0] = dx - ux - vx; Py[0] = dy - uy - vy;
        Px[1] = dx + ux - vx; Py[1] = dy + uy - vy;
        Px[2] = dx + ux + vx; Py[2] = dy + uy + vy;
        Px[3] = dx - ux + vx; Py[3] = dy - uy + vy;

        // ---- pass 1: clip each quad edge against x-slab [-hw2, hw2].
        // Each edge unconditionally emits its clipped sub-segment endpoints
        // (degenerate edges collapse; emitted x clamped onto the slab, so any
        // spurious points are colinear with the chord on x=±hw2 -> zero area).
        const float lo = -hw2, hi = hw2;
        float Sx[8], Sy[8];
        #pragma unroll
        for (int k = 0; k < 4; k++) {
            int kn = (k + 1) & 3;
            float cx = Px[k], cy = Py[k];
            float rx = Px[kn] - cx, ry = Py[kn] - cy;
            float inv = frcp(rx);
            float tl = (lo - cx) * inv, th = (hi - cx) * inv;
            float ta = fminf(tl, th), tb = fmaxf(tl, th);
            float t0 = clampf(ta, 0.0f, 1.0f);
            float t1 = clampf(tb, 0.0f, 1.0f);
            Sx[2 * k]     = clampf(fmaf(t0, rx, cx), lo, hi);
            Sy[2 * k]     = fmaf(t0, ry, cy);
            Sx[2 * k + 1] = clampf(fmaf(t1, rx, cx), lo, hi);
            Sy[2 * k + 1] = fmaf(t1, ry, cy);
        }

        // ---- pass 2: clip 8-gon edges against y-slab [-hh2, hh2], stream
        // shoelace over the 16 unconditionally-emitted points.
        const float lo2 = -hh2, hi2 = hh2;
        float acc = 0.0f;
        float prevx = 0.0f, prevy = 0.0f, fx = 0.0f, fy = 0.0f;
        #pragma unroll
        for (int k = 0; k < 8; k++) {
            int kn = (k + 1) & 7;
            float cx = Sx[k], cy = Sy[k];
            float rx = Sx[kn] - cx, ry = Sy[kn] - cy;
            float inv = frcp(ry);
            float tl = (lo2 - cy) * inv, th = (hi2 - cy) * inv;
            float ta = fminf(tl, th), tb = fmaxf(tl, th);
            float t0 = clampf(ta, 0.0f, 1.0f);
            float t1 = clampf(tb, 0.0f, 1.0f);
            float e0x = fmaf(t0, rx, cx);
            float e0y = clampf(fmaf(t0, ry, cy), lo2, hi2);
            float e1x = fmaf(t1, rx, cx);
            float e1y = clampf(fmaf(t1, ry, cy), lo2, hi2);
            if (k == 0) { fx = e0x; fy = e0y; }
            else        { acc += fmaf(prevx, e0y, -(prevy * e0x)); }
            acc += fmaf(e0x, e1y, -(e0y * e1x));
            prevx = e1x; prevy = e1y;
        }
        acc += fmaf(prevx, fy, -(prevy * fx));

        float area = 0.5f * fabsf(acc);
        float A1 = 4.0f * hw1 * hh1, A2 = 4.0f * hw2 * hh2;
        float iou = area / fmaxf(A1 + A2 - area, 1e-10f);
        loss = -__logf(fmaxf(iou, 1e-6f));
    }

    // ---- block reduction ----
    #pragma unroll
    for (int o = 16; o > 0; o >>= 1)
        loss += __shfl_down_sync(0xFFFFFFFFu, loss, o);
    int lane = tid & 31, warp = tid >> 5;
    if (lane == 0) ssum[warp] = (double)loss;
    __syncthreads();

    if (tid == 0) {
        double t = 0.0;
        #pragma unroll
        for (int w = 0; w < NT / 32; w++) t += ssum[w];
        atomicAdd(&g_acc, t);
        __threadfence();
        unsigned int done = atomicAdd(&g_cnt, 1u);
        if (done == (unsigned int)(nblocks - 1)) {
            double a = atomicAdd(&g_acc, 0.0);
            out[0] = (float)(a / (double)n);
            atomicExch((unsigned long long*)&g_acc, 0ull);
            atomicExch(&g_cnt, 0u);
        }
    }
}

extern "C" void kernel_launch(void* const* d_in, const int* in_sizes, int n_in,
                              void* d_out, int out_size) {
    const float* pred = (const float*)d_in[0];
    const float* tgt  = (const float*)d_in[1];
    int n = in_sizes[0] / 5;
    int nblocks = (n + NT - 1) / NT;
    k_loss<<<nblocks, NT>>>(pred, tgt, (float*)d_out, n, nblocks);
}

// round 8
// speedup vs baseline: 3.8664x; 1.0151x over previous
#include <cuda_runtime.h>

#define NT 256

__device__ double       g_acc;
__device__ unsigned int g_cnt;

__device__ __forceinline__ float frcp(float x) {
    float r; asm("rcp.approx.f32 %0, %1;" : "=f"(r) : "f"(x)); return r;
}
__device__ __forceinline__ float clampf(float x, float lo, float hi) {
    return fminf(fmaxf(x, lo), hi);
}

// Pass-2 streaming state: y-clip each incoming 8-gon edge and fold the two
// unconditionally-emitted points into the running shoelace chain.
struct Chain {
    float acc, px, py, fx, fy;
};

__device__ __forceinline__ void edge2(float cx, float cy, float nx, float ny,
                                      float lo2, float hi2, Chain& s, bool first) {
    float rx = nx - cx, ry = ny - cy;
    float inv = frcp(ry);
    float tl = (lo2 - cy) * inv, th = (hi2 - cy) * inv;
    float ta = fminf(tl, th), tb = fmaxf(tl, th);
    float t0 = clampf(ta, 0.0f, 1.0f);
    float t1 = clampf(tb, 0.0f, 1.0f);
    float e0x = fmaf(t0, rx, cx);
    float e0y = clampf(fmaf(t0, ry, cy), lo2, hi2);
    float e1x = fmaf(t1, rx, cx);
    float e1y = clampf(fmaf(t1, ry, cy), lo2, hi2);
    if (first) { s.fx = e0x; s.fy = e0y; }
    else       { s.acc += fmaf(s.px, e0y, -(s.py * e0x)); }
    s.acc += fmaf(e0x, e1y, -(e0y * e1x));
    s.px = e1x; s.py = e1y;
}

__global__ void __launch_bounds__(NT, 5)
k_loss(const float* __restrict__ pred, const float* __restrict__ tgt,
       float* __restrict__ out, int n, int nblocks) {
    __shared__ double ssum[NT / 32];

    const int tid = threadIdx.x;
    const int i   = blockIdx.x * NT + tid;

    float loss = 0.0f;
    if (i < n) {
        const float* p = pred + (size_t)i * 5;
        const float* q = tgt  + (size_t)i * 5;
        float x1 = p[0], y1 = p[1], hw1 = 0.5f * p[2], hh1 = 0.5f * p[3], a1 = p[4];
        float x2 = q[0], y2 = q[1], hw2 = 0.5f * q[2], hh2 = 0.5f * q[3], a2 = q[4];

        // Box2's local frame: clip region is the axis box [±hw2]x[±hh2].
        float sf, cf, s2, c2;
        __sincosf(a1 - a2, &sf, &cf);
        __sincosf(a2, &s2, &c2);
        float ddx = x1 - x2, ddy = y1 - y2;
        float dx = fmaf(ddx, c2, ddy * s2);
        float dy = fmaf(-ddx, s2, ddy * c2);

        float ux = hw1 * cf, uy = hw1 * sf;
        float vx = -hh1 * sf, vy = hh1 * cf;
        float Px[4], Py[4];
        Px[0] = dx - ux - vx; Py[0] = dy - uy - vy;
        Px[1] = dx + ux - vx; Py[1] = dy + uy - vy;
        Px[2] = dx + ux + vx; Py[2] = dy + uy + vy;
        Px[3] = dx - ux + vx; Py[3] = dy - uy + vy;

        const float lo = -hw2, hi = hw2;
        const float lo2 = -hh2, hi2 = hh2;

        Chain st; st.acc = 0.0f; st.px = st.py = st.fx = st.fy = 0.0f;
        float F8x = 0.0f, F8y = 0.0f, p8x = 0.0f, p8y = 0.0f;

        // Fused: x-slab clip each quad edge (emit 2 pts), stream the emitted
        // 8-gon vertices directly through the y-slab clip + shoelace chain.
        #pragma unroll
        for (int k = 0; k < 4; k++) {
            int kn = (k + 1) & 3;
            float cx = Px[k], cy = Py[k];
            float rx = Px[kn] - cx, ry = Py[kn] - cy;
            float inv = frcp(rx);
            float tl = (lo - cx) * inv, th = (hi - cx) * inv;
            float ta = fminf(tl, th), tb = fmaxf(tl, th);
            float t0 = clampf(ta, 0.0f, 1.0f);
            float t1 = clampf(tb, 0.0f, 1.0f);
            float v0x = clampf(fmaf(t0, rx, cx), lo, hi);
            float v0y = fmaf(t0, ry, cy);
            float v1x = clampf(fmaf(t1, rx, cx), lo, hi);
            float v1y = fmaf(t1, ry, cy);
            if (k == 0) {
                F8x = v0x; F8y = v0y;
                edge2(v0x, v0y, v1x, v1y, lo2, hi2, st, true);
            } else {
                edge2(p8x, p8y, v0x, v0y, lo2, hi2, st, false);
                edge2(v0x, v0y, v1x, v1y, lo2, hi2, st, false);
            }
            p8x = v1x; p8y = v1y;
        }
        edge2(p8x, p8y, F8x, F8y, lo2, hi2, st, false);   // close the 8-gon
        st.acc += fmaf(st.px, st.fy, -(st.py * st.fx));   // close the 16-gon

        float area = 0.5f * fabsf(st.acc);
        float A1 = 4.0f * hw1 * hh1, A2 = 4.0f * hw2 * hh2;
        float iou = area / fmaxf(A1 + A2 - area, 1e-10f);
        loss = -__logf(fmaxf(iou, 1e-6f));
    }

    // ---- block reduction ----
    #pragma unroll
    for (int o = 16; o > 0; o >>= 1)
        loss += __shfl_down_sync(0xFFFFFFFFu, loss, o);
    int lane = tid & 31, warp = tid >> 5;
    if (lane == 0) ssum[warp] = (double)loss;
    __syncthreads();

    if (tid == 0) {
        double t = 0.0;
        #pragma unroll
        for (int w = 0; w < NT / 32; w++) t += ssum[w];
        atomicAdd(&g_acc, t);
        __threadfence();
        unsigned int done = atomicAdd(&g_cnt, 1u);
        if (done == (unsigned int)(nblocks - 1)) {
            double a = atomicAdd(&g_acc, 0.0);
            out[0] = (float)(a / (double)n);
            atomicExch((unsigned long long*)&g_acc, 0ull);
            atomicExch(&g_cnt, 0u);
        }
    }
}

extern "C" void kernel_launch(void* const* d_in, const int* in_sizes, int n_in,
                              void* d_out, int out_size) {
    const float* pred = (const float*)d_in[0];
    const float* tgt  = (const float*)d_in[1];
    int n = in_sizes[0] / 5;
    int nblocks = (n + NT - 1) / NT;
    k_loss<<<nblocks, NT>>>(pred, tgt, (float*)d_out, n, nblocks);
}